// round 16
// baseline (speedup 1.0000x reference)
#include <cuda_runtime.h>

// Problem constants (dataset-fixed shapes; margins included).
#define MAXN 50048
#define MAXE 1000000
#define WPTOT 45312  // total u64 elems of all interleaved weights

// Scratch (module-level device arrays; 16B-aligned; zero-init at module load).
__device__ __align__(16) int   g_cnt[MAXN];
__device__ __align__(16) int   g_off[MAXN];
__device__ __align__(16) int   g_cursor[MAXN];
__device__ __align__(16) int   g_partial[256];
__device__ __align__(16) int   g_csr_src[MAXE];
__device__ __align__(16) float g_dinv[MAXN];
__device__ __align__(16) float g_y[MAXN * 96];       // scaled input / scratch
__device__ __align__(16) float g_agg[MAXN * 96];     // aggregated features
__device__ __align__(16) float g_bufA[MAXN * 256];
__device__ __align__(16) float g_bufB[MAXN * 256];
__device__ __align__(16) unsigned long long g_wp[WPTOT];

// Interleaved weight offsets (u64 units).
#define OW1 0          // 64x96  -> 32*96  = 3072
#define OW2 3072       // 96x96  -> 48*96  = 4608
#define OW3 7680       // 96x96  -> 48*96  = 4608
#define OL1 12288      // 96x256 -> 48*256 = 12288
#define OL2 24576      // 256x128-> 128*128= 16384
#define OL3 40960      // 128x64 -> 64*64  = 4096
#define OL4 45056      // 64x8   -> 32*8   = 256

// ---------------------------------------------------------------------------
// Weight interleave: Wp[off + m2*K + c] = pack(W[2m2*K+c], W[(2m2+1)*K+c]).
// ---------------------------------------------------------------------------
struct WSeg { const float* src; int K; int off; int sz; };
struct WSegs { WSeg s[7]; };

__global__ void interleave_kernel(WSegs segs, unsigned long long* __restrict__ Wp) {
    int idx = blockIdx.x * blockDim.x + threadIdx.x;
#pragma unroll
    for (int k = 0; k < 7; k++) {
        if (idx < segs.s[k].sz) {
            int K = segs.s[k].K;
            int m2 = idx / K;
            int c = idx - m2 * K;
            const float* src = segs.s[k].src;
            unsigned int lo = __float_as_uint(src[(2 * m2) * K + c]);
            unsigned int hi = __float_as_uint(src[(2 * m2 + 1) * K + c]);
            Wp[segs.s[k].off + idx] = (unsigned long long)lo | ((unsigned long long)hi << 32);
            return;
        }
        idx -= segs.s[k].sz;
    }
}

// ---------------------------------------------------------------------------
// CSR build (edge_index is int32). cnt zeroed at graph end.
// ---------------------------------------------------------------------------
__global__ void count_kernel(const int* __restrict__ ei, int E,
                             int* __restrict__ cnt) {
    int e = blockIdx.x * blockDim.x + threadIdx.x;
    if (e < E) atomicAdd(&cnt[ei[E + e]], 1);
}

__global__ void dinv_kernel(const int* __restrict__ cnt, float* __restrict__ dinv,
                            int n) {
    int i = blockIdx.x * blockDim.x + threadIdx.x;
    if (i < n) dinv[i] = rsqrtf(1.0f + (float)cnt[i]);
}

__global__ void scan1_kernel(const int* __restrict__ cnt, int n,
                             int* __restrict__ off, int* __restrict__ partial) {
    __shared__ int sm[1024];
    int t = threadIdx.x;
    int i = blockIdx.x * 1024 + t;
    int v = (i < n) ? cnt[i] : 0;
    sm[t] = v;
    __syncthreads();
#pragma unroll
    for (int ofs = 1; ofs < 1024; ofs <<= 1) {
        int add = (t >= ofs) ? sm[t - ofs] : 0;
        __syncthreads();
        sm[t] += add;
        __syncthreads();
    }
    if (i < n) off[i] = sm[t] - v;
    if (t == 1023) partial[blockIdx.x] = sm[t];
}

__global__ void scan2_kernel(int* __restrict__ partial, int nb) {
    __shared__ int sm[256];
    int t = threadIdx.x;
    int v = (t < nb) ? partial[t] : 0;
    sm[t] = v;
    __syncthreads();
#pragma unroll
    for (int ofs = 1; ofs < 256; ofs <<= 1) {
        int add = (t >= ofs) ? sm[t - ofs] : 0;
        __syncthreads();
        sm[t] += add;
        __syncthreads();
    }
    if (t < nb) partial[t] = sm[t] - v;
}

__global__ void scan3_kernel(int* __restrict__ off, const int* __restrict__ partial,
                             int* __restrict__ cursor, int n) {
    int i = blockIdx.x * blockDim.x + threadIdx.x;
    if (i < n) {
        int o = off[i] + partial[i >> 10];
        off[i] = o;
        cursor[i] = o;
    }
}

__global__ void fill_kernel(const int* __restrict__ ei, int E,
                            int* __restrict__ cursor, int* __restrict__ csr_src) {
    int e = blockIdx.x * blockDim.x + threadIdx.x;
    if (e < E) {
        int s = ei[e];
        int d = ei[E + e];
        int pos = atomicAdd(&cursor[d], 1);
        csr_src[pos] = s;
    }
}

__global__ void zero_cnt_kernel(int* __restrict__ cnt, int n) {
    int i = blockIdx.x * blockDim.x + threadIdx.x;
    if (i < n) cnt[i] = 0;
}

// ---------------------------------------------------------------------------
// Y = dinv ⊙ X  (row scale), thread per (node, 4 channels).
// ---------------------------------------------------------------------------
template <int C4>
__global__ void scale_kernel(const float* __restrict__ X,
                             const float* __restrict__ dinv,
                             float* __restrict__ Y, int n) {
    int idx = blockIdx.x * blockDim.x + threadIdx.x;
    if (idx >= n * C4) return;
    int node = idx / C4;
    float d = dinv[node];
    float4 x = reinterpret_cast<const float4*>(X)[idx];
    reinterpret_cast<float4*>(Y)[idx] =
        make_float4(x.x * d, x.y * d, x.z * d, x.w * d);
}

// ---------------------------------------------------------------------------
// Aggregation on pre-scaled Y: Z[v] = dinv[v] * (Y[v] + sum_u Y[u]).
// Thread per (node, 8 channels); pure adds in the loop.
// ---------------------------------------------------------------------------
template <int C8>
__global__ void __launch_bounds__(256)
agg_kernel(const int* __restrict__ off, const int* __restrict__ cnt,
           const int* __restrict__ csr_src, const float* __restrict__ dinv,
           const float* __restrict__ Y, float* __restrict__ Z, int n) {
    int idx = blockIdx.x * blockDim.x + threadIdx.x;
    int node = idx / C8;
    int c8 = idx - node * C8;
    if (node >= n) return;

    const float4* Y4 = reinterpret_cast<const float4*>(Y);
    const size_t S4 = C8 * 2;
    size_t base = (size_t)node * S4 + c8 * 2;
    float4 acc0 = __ldg(Y4 + base);
    float4 acc1 = __ldg(Y4 + base + 1);

    int start = off[node];
    int deg = cnt[node];
    const int* cp = csr_src + start;

    int j = 0;
    for (; j + 4 <= deg; j += 4) {
        int s0 = __ldg(cp + j);
        int s1 = __ldg(cp + j + 1);
        int s2 = __ldg(cp + j + 2);
        int s3 = __ldg(cp + j + 3);
        size_t b0 = (size_t)s0 * S4 + c8 * 2;
        size_t b1 = (size_t)s1 * S4 + c8 * 2;
        size_t b2 = (size_t)s2 * S4 + c8 * 2;
        size_t b3 = (size_t)s3 * S4 + c8 * 2;
        float4 p00 = __ldg(Y4 + b0), p01 = __ldg(Y4 + b0 + 1);
        float4 p10 = __ldg(Y4 + b1), p11 = __ldg(Y4 + b1 + 1);
        float4 p20 = __ldg(Y4 + b2), p21 = __ldg(Y4 + b2 + 1);
        float4 p30 = __ldg(Y4 + b3), p31 = __ldg(Y4 + b3 + 1);
        acc0.x += p00.x; acc0.y += p00.y; acc0.z += p00.z; acc0.w += p00.w;
        acc1.x += p01.x; acc1.y += p01.y; acc1.z += p01.z; acc1.w += p01.w;
        acc0.x += p10.x; acc0.y += p10.y; acc0.z += p10.z; acc0.w += p10.w;
        acc1.x += p11.x; acc1.y += p11.y; acc1.z += p11.z; acc1.w += p11.w;
        acc0.x += p20.x; acc0.y += p20.y; acc0.z += p20.z; acc0.w += p20.w;
        acc1.x += p21.x; acc1.y += p21.y; acc1.z += p21.z; acc1.w += p21.w;
        acc0.x += p30.x; acc0.y += p30.y; acc0.z += p30.z; acc0.w += p30.w;
        acc1.x += p31.x; acc1.y += p31.y; acc1.z += p31.z; acc1.w += p31.w;
    }
    for (; j < deg; j++) {
        int s = __ldg(cp + j);
        size_t bb = (size_t)s * S4 + c8 * 2;
        float4 p0 = __ldg(Y4 + bb), p1 = __ldg(Y4 + bb + 1);
        acc0.x += p0.x; acc0.y += p0.y; acc0.z += p0.z; acc0.w += p0.w;
        acc1.x += p1.x; acc1.y += p1.y; acc1.z += p1.z; acc1.w += p1.w;
    }

    float d = dinv[node];
    float4* Z4 = reinterpret_cast<float4*>(Z);
    Z4[base] = make_float4(acc0.x * d, acc0.y * d, acc0.z * d, acc0.w * d);
    Z4[base + 1] = make_float4(acc1.x * d, acc1.y * d, acc1.z * d, acc1.w * d);
}

// ---------------------------------------------------------------------------
// GEMM (k-pair weights): C[n,K] = A[n,M] @ W[M,K].
// gemm42: 4 nodes x 8 cols per thread (W bytes/FMA2: 6 -> 4; fma cap 33->50%).
// EPI: 1 bias+relu, 2 bias, 3 bias+BN+relu, 4 = 3 then *dinv, 5 = *dinv only.
// ---------------------------------------------------------------------------
#define FMA2(acc, a, w) \
    asm("fma.rn.f32x2 %0, %1, %2, %0;" : "+l"(acc) : "l"(a), "l"(w))

template <int M, int K, int EPI>
__global__ void __launch_bounds__(128, 4)
gemm42_kernel(const float* __restrict__ A, const unsigned long long* __restrict__ Wp,
              const float* __restrict__ bias, const float* __restrict__ gamma,
              const float* __restrict__ beta, const float* __restrict__ dinv,
              float* __restrict__ C, int n) {
    constexpr int KC2 = K / 8;  // 8-col groups
    constexpr int KC4 = K / 4;  // float4 per output row
    constexpr int MS = M / 4;   // ulonglong2 per A row
    int idx = blockIdx.x * blockDim.x + threadIdx.x;
    int ng = idx / KC2;
    int cg = idx - ng * KC2;
    int n0 = ng * 4;
    if (n0 >= n) return;

    int ni[4];
#pragma unroll
    for (int i = 0; i < 4; i++) ni[i] = (n0 + i < n) ? (n0 + i) : n0;

    const ulonglong2* A2 = reinterpret_cast<const ulonglong2*>(A);
    unsigned long long acc[4][8] = {};  // [node][col], even-k lo / odd-k hi

#pragma unroll 2
    for (int m4 = 0; m4 < MS; m4++) {
        ulonglong2 av[4];
#pragma unroll
        for (int i = 0; i < 4; i++)
            av[i] = __ldg(A2 + (size_t)ni[i] * MS + m4);
        const ulonglong2* w0p = reinterpret_cast<const ulonglong2*>(
            Wp + (size_t)(2 * m4) * K + cg * 8);
        const ulonglong2* w1p = reinterpret_cast<const ulonglong2*>(
            Wp + (size_t)(2 * m4 + 1) * K + cg * 8);
        ulonglong2 w0a = __ldg(w0p),     w0b = __ldg(w0p + 1);
        ulonglong2 w0c = __ldg(w0p + 2), w0d = __ldg(w0p + 3);
        ulonglong2 w1a = __ldg(w1p),     w1b = __ldg(w1p + 1);
        ulonglong2 w1c = __ldg(w1p + 2), w1d = __ldg(w1p + 3);
        unsigned long long w0[8] = {w0a.x, w0a.y, w0b.x, w0b.y,
                                    w0c.x, w0c.y, w0d.x, w0d.y};
        unsigned long long w1[8] = {w1a.x, w1a.y, w1b.x, w1b.y,
                                    w1c.x, w1c.y, w1d.x, w1d.y};
#pragma unroll
        for (int i = 0; i < 4; i++) {
#pragma unroll
            for (int c = 0; c < 8; c++) {
                FMA2(acc[i][c], av[i].x, w0[c]);
                FMA2(acc[i][c], av[i].y, w1[c]);
            }
        }
    }

    float4 bv[2], gs[2], bev[2];
#pragma unroll
    for (int h = 0; h < 2; h++) {
        bv[h] = make_float4(0.f, 0.f, 0.f, 0.f);
        gs[h] = make_float4(0.f, 0.f, 0.f, 0.f);
        bev[h] = make_float4(0.f, 0.f, 0.f, 0.f);
    }
    if (EPI >= 1 && EPI <= 4) {
        bv[0] = reinterpret_cast<const float4*>(bias)[cg * 2];
        bv[1] = reinterpret_cast<const float4*>(bias)[cg * 2 + 1];
    }
    if (EPI == 3 || EPI == 4) {
        const float INV = 0.99999500003749971f;  // 1/sqrt(1+1e-5)
#pragma unroll
        for (int h = 0; h < 2; h++) {
            float4 gv = reinterpret_cast<const float4*>(gamma)[cg * 2 + h];
            gs[h] = make_float4(gv.x * INV, gv.y * INV, gv.z * INV, gv.w * INV);
            bev[h] = reinterpret_cast<const float4*>(beta)[cg * 2 + h];
        }
    }

#pragma unroll
    for (int i = 0; i < 4; i++) {
        int node = n0 + i;
        if (node >= n) break;
        float d = (EPI == 4 || EPI == 5) ? dinv[node] : 1.0f;
#pragma unroll
        for (int h = 0; h < 2; h++) {
            float o[4];
#pragma unroll
            for (int c = 0; c < 4; c++) {
                unsigned long long v = acc[i][h * 4 + c];
                float lo = __uint_as_float((unsigned int)v);
                float hi = __uint_as_float((unsigned int)(v >> 32));
                o[c] = lo + hi;
            }
            float4 r = make_float4(o[0], o[1], o[2], o[3]);
            if (EPI == 1 || EPI == 2) {
                r.x += bv[h].x; r.y += bv[h].y; r.z += bv[h].z; r.w += bv[h].w;
                if (EPI == 1) {
                    r.x = fmaxf(r.x, 0.f); r.y = fmaxf(r.y, 0.f);
                    r.z = fmaxf(r.z, 0.f); r.w = fmaxf(r.w, 0.f);
                }
            } else if (EPI == 3 || EPI == 4) {
                r.x = fmaxf(fmaf(r.x + bv[h].x, gs[h].x, bev[h].x), 0.f) * d;
                r.y = fmaxf(fmaf(r.y + bv[h].y, gs[h].y, bev[h].y), 0.f) * d;
                r.z = fmaxf(fmaf(r.z + bv[h].z, gs[h].z, bev[h].z), 0.f) * d;
                r.w = fmaxf(fmaf(r.w + bv[h].w, gs[h].w, bev[h].w), 0.f) * d;
            } else if (EPI == 5) {
                r.x *= d; r.y *= d; r.z *= d; r.w *= d;
            }
            reinterpret_cast<float4*>(C)[(size_t)node * KC4 + cg * 2 + h] = r;
        }
    }
}

// Narrow-K fallback (K=8): 4 nodes x 4 cols.
template <int M, int K, int EPI>
__global__ void __launch_bounds__(128, 6)
gemm4p_kernel(const float* __restrict__ A, const unsigned long long* __restrict__ Wp,
              const float* __restrict__ bias, float* __restrict__ C, int n) {
    constexpr int KC = K / 4;
    constexpr int MS = M / 4;
    int idx = blockIdx.x * blockDim.x + threadIdx.x;
    int ng = idx / KC;
    int c4 = idx - ng * KC;
    int n0 = ng * 4;
    if (n0 >= n) return;

    int ni[4];
#pragma unroll
    for (int i = 0; i < 4; i++) ni[i] = (n0 + i < n) ? (n0 + i) : n0;

    const ulonglong2* A2 = reinterpret_cast<const ulonglong2*>(A);
    unsigned long long acc[4][4] = {};

#pragma unroll 4
    for (int m4 = 0; m4 < MS; m4++) {
        ulonglong2 av[4];
#pragma unroll
        for (int i = 0; i < 4; i++)
            av[i] = __ldg(A2 + (size_t)ni[i] * MS + m4);
        const ulonglong2* w0p = reinterpret_cast<const ulonglong2*>(
            Wp + (size_t)(2 * m4) * K) + c4 * 2;
        const ulonglong2* w1p = reinterpret_cast<const ulonglong2*>(
            Wp + (size_t)(2 * m4 + 1) * K) + c4 * 2;
        ulonglong2 w0a = __ldg(w0p), w0b = __ldg(w0p + 1);
        ulonglong2 w1a = __ldg(w1p), w1b = __ldg(w1p + 1);
        unsigned long long w0[4] = {w0a.x, w0a.y, w0b.x, w0b.y};
        unsigned long long w1[4] = {w1a.x, w1a.y, w1b.x, w1b.y};
#pragma unroll
        for (int i = 0; i < 4; i++) {
#pragma unroll
            for (int c = 0; c < 4; c++) {
                FMA2(acc[i][c], av[i].x, w0[c]);
                FMA2(acc[i][c], av[i].y, w1[c]);
            }
        }
    }

    float4 bv = reinterpret_cast<const float4*>(bias)[c4];
#pragma unroll
    for (int i = 0; i < 4; i++) {
        int node = n0 + i;
        if (node >= n) break;
        float o[4];
#pragma unroll
        for (int c = 0; c < 4; c++) {
            unsigned long long v = acc[i][c];
            o[c] = __uint_as_float((unsigned int)v) +
                   __uint_as_float((unsigned int)(v >> 32));
        }
        float4 r = make_float4(o[0] + bv.x, o[1] + bv.y, o[2] + bv.z, o[3] + bv.w);
        if (EPI == 1) {
            r.x = fmaxf(r.x, 0.f); r.y = fmaxf(r.y, 0.f);
            r.z = fmaxf(r.z, 0.f); r.w = fmaxf(r.w, 0.f);
        }
        reinterpret_cast<float4*>(C)[(size_t)node * KC + c4] = r;
    }
}

// ---------------------------------------------------------------------------
// Launch
// ---------------------------------------------------------------------------
static inline int grid_for(long long threads, int block) {
    return (int)((threads + block - 1) / block);
}

extern "C" void kernel_launch(void* const* d_in, const int* in_sizes, int n_in,
                              void* d_out, int out_size) {
    const float* x  = (const float*)d_in[0];
    const int*   ei = (const int*)d_in[1];
    const float* w1 = (const float*)d_in[2];
    const float* b1 = (const float*)d_in[3];
    const float* g1 = (const float*)d_in[4];
    const float* be1 = (const float*)d_in[5];
    const float* w2 = (const float*)d_in[6];
    const float* b2 = (const float*)d_in[7];
    const float* g2 = (const float*)d_in[8];
    const float* be2 = (const float*)d_in[9];
    const float* w3 = (const float*)d_in[10];
    const float* b3 = (const float*)d_in[11];
    const float* g3 = (const float*)d_in[12];
    const float* be3 = (const float*)d_in[13];
    const float* lw1 = (const float*)d_in[14];
    const float* lb1 = (const float*)d_in[15];
    const float* lw2 = (const float*)d_in[16];
    const float* lb2 = (const float*)d_in[17];
    const float* lw3 = (const float*)d_in[18];
    const float* lb3 = (const float*)d_in[19];
    const float* lw4 = (const float*)d_in[20];
    const float* lb4 = (const float*)d_in[21];
    float* out = (float*)d_out;

    const int N = in_sizes[0] / 64;
    const int E = in_sizes[1] / 2;

    int *cnt, *off, *cursor, *partial, *csr_src;
    float *dinv, *y, *agg, *bufA, *bufB;
    unsigned long long* wp;
    cudaGetSymbolAddress((void**)&cnt,     g_cnt);
    cudaGetSymbolAddress((void**)&off,     g_off);
    cudaGetSymbolAddress((void**)&cursor,  g_cursor);
    cudaGetSymbolAddress((void**)&partial, g_partial);
    cudaGetSymbolAddress((void**)&csr_src, g_csr_src);
    cudaGetSymbolAddress((void**)&dinv,    g_dinv);
    cudaGetSymbolAddress((void**)&y,       g_y);
    cudaGetSymbolAddress((void**)&agg,     g_agg);
    cudaGetSymbolAddress((void**)&bufA,    g_bufA);
    cudaGetSymbolAddress((void**)&bufB,    g_bufB);
    cudaGetSymbolAddress((void**)&wp,      g_wp);

    const int BLK = 256;
    const int GB = 128;
    const int nb = (N + 1023) / 1024;
    const long long ngrp = (N + 3) / 4;

    // 0: interleave weights.
    WSegs segs;
    segs.s[0] = {w1,  96,  OW1, 32 * 96};
    segs.s[1] = {w2,  96,  OW2, 48 * 96};
    segs.s[2] = {w3,  96,  OW3, 48 * 96};
    segs.s[3] = {lw1, 256, OL1, 48 * 256};
    segs.s[4] = {lw2, 128, OL2, 128 * 128};
    segs.s[5] = {lw3, 64,  OL3, 64 * 64};
    segs.s[6] = {lw4, 8,   OL4, 32 * 8};
    interleave_kernel<<<grid_for(WPTOT, BLK), BLK>>>(segs, wp);

    // 1-2: degree + dinv.
    count_kernel<<<grid_for(E, BLK), BLK>>>(ei, E, cnt);
    dinv_kernel<<<grid_for(N, BLK), BLK>>>(cnt, dinv, N);

    // 3 (PROFILED SLOT): probe — gemm42<96,256> on 2048 nodes. Output junk in
    // bufB, fully overwritten by the real lw1 GEMM below; deterministic.
    gemm42_kernel<96, 256, 1><<<grid_for(512LL * 32, GB), GB>>>(bufA, wp + OL1, lb1, nullptr, nullptr, nullptr, bufB, 2048);

    // CSR scan + fill.
    scan1_kernel<<<nb, 1024>>>(cnt, N, off, partial);
    scan2_kernel<<<1, 256>>>(partial, nb);
    scan3_kernel<<<grid_for(N, BLK), BLK>>>(off, partial, cursor, N);
    fill_kernel<<<grid_for(E, BLK), BLK>>>(ei, E, cursor, csr_src);

    // Layer 1: Y0 = dinv*x (64ch), agg, GEMM 64->96 (BN+ReLU, pre-scale out).
    scale_kernel<16><<<grid_for((long long)N * 16, BLK), BLK>>>(x, dinv, y, N);
    agg_kernel<8><<<grid_for((long long)N * 8, BLK), BLK>>>(off, cnt, csr_src, dinv, y, agg, N);
    gemm42_kernel<64, 96, 4><<<grid_for(ngrp * 12, GB), GB>>>(agg, wp + OW1, b1, g1, be1, dinv, bufA, N);

    // Layer 2.
    agg_kernel<12><<<grid_for((long long)N * 12, BLK), BLK>>>(off, cnt, csr_src, dinv, bufA, agg, N);
    gemm42_kernel<96, 96, 4><<<grid_for(ngrp * 12, GB), GB>>>(agg, wp + OW2, b2, g2, be2, dinv, bufB, N);

    // Layer 3 (no pre-scale).
    agg_kernel<12><<<grid_for((long long)N * 12, BLK), BLK>>>(off, cnt, csr_src, dinv, bufB, agg, N);
    gemm42_kernel<96, 96, 3><<<grid_for(ngrp * 12, GB), GB>>>(agg, wp + OW3, b3, g3, be3, nullptr, bufA, N);

    // MLP head.
    gemm42_kernel<96, 256, 1><<<grid_for(ngrp * 32, GB), GB>>>(bufA, wp + OL1, lb1, nullptr, nullptr, nullptr, bufB, N);
    gemm42_kernel<256, 128, 1><<<grid_for(ngrp * 16, GB), GB>>>(bufB, wp + OL2, lb2, nullptr, nullptr, nullptr, bufA, N);
    gemm42_kernel<128, 64, 1><<<grid_for(ngrp * 8, GB), GB>>>(bufA, wp + OL3, lb3, nullptr, nullptr, nullptr, bufB, N);
    gemm4p_kernel<64, 8, 2><<<grid_for(ngrp * 2, GB), GB>>>(bufB, wp + OL4, lb4, out, N);

    // Reset cnt for next replay.
    zero_cnt_kernel<<<grid_for(N, BLK), BLK>>>(cnt, N);
}

// round 17
// speedup vs baseline: 1.3518x; 1.3518x over previous
#include <cuda_runtime.h>

// Problem constants (dataset-fixed shapes; margins included).
#define MAXN 50048
#define MAXE 1000000
#define WPTOT 45312  // total u64 elems of all interleaved weights

// Scratch (module-level device arrays; 16B-aligned; zero-init at module load).
__device__ __align__(16) int   g_cnt[MAXN];          // zeroed at graph end
__device__ __align__(16) int   g_off[MAXN];
__device__ __align__(16) int   g_cursor[MAXN];
__device__ __align__(16) int   g_partial[256];
__device__ __align__(16) int   g_csr_src[MAXE];
__device__ __align__(16) float g_dinv[MAXN];
__device__ __align__(16) float g_agg[MAXN * 96];
__device__ __align__(16) float g_bufA[MAXN * 256];
__device__ __align__(16) float g_bufB[MAXN * 256];
__device__ __align__(16) unsigned long long g_wp[WPTOT];

// Interleaved weight offsets (u64 units).
#define OW1 0          // 64x96  -> 3072
#define OW2 3072       // 96x96  -> 4608
#define OW3 7680       // 96x96  -> 4608
#define OL1 12288      // 96x256 -> 12288
#define OL2 24576      // 256x128-> 16384
#define OL3 40960      // 128x64 -> 4096
#define OL4 45056      // 64x8   -> 256

// ---------------------------------------------------------------------------
// Weight interleave: Wp[off + m2*K + c] = pack(W[2m2*K+c], W[(2m2+1)*K+c]).
// ---------------------------------------------------------------------------
struct WSeg { const float* src; int K; int off; int sz; };
struct WSegs { WSeg s[7]; };

__global__ void interleave_kernel(WSegs segs, unsigned long long* __restrict__ Wp) {
    int idx = blockIdx.x * blockDim.x + threadIdx.x;
#pragma unroll
    for (int k = 0; k < 7; k++) {
        if (idx < segs.s[k].sz) {
            int K = segs.s[k].K;
            int m2 = idx / K;
            int c = idx - m2 * K;
            const float* src = segs.s[k].src;
            unsigned int lo = __float_as_uint(src[(2 * m2) * K + c]);
            unsigned int hi = __float_as_uint(src[(2 * m2 + 1) * K + c]);
            Wp[segs.s[k].off + idx] = (unsigned long long)lo | ((unsigned long long)hi << 32);
            return;
        }
        idx -= segs.s[k].sz;
    }
}

// ---------------------------------------------------------------------------
// CSR build (edge_index is int32). cnt zero at entry; re-zeroed at graph end.
// ---------------------------------------------------------------------------
__global__ void count_kernel(const int* __restrict__ ei, int E,
                             int* __restrict__ cnt) {
    int e = blockIdx.x * blockDim.x + threadIdx.x;
    if (e < E) atomicAdd(&cnt[ei[E + e]], 1);
}

__global__ void scan1_kernel(const int* __restrict__ cnt, int n,
                             int* __restrict__ off, int* __restrict__ partial) {
    __shared__ int sm[1024];
    int t = threadIdx.x;
    int i = blockIdx.x * 1024 + t;
    int v = (i < n) ? cnt[i] : 0;
    sm[t] = v;
    __syncthreads();
#pragma unroll
    for (int ofs = 1; ofs < 1024; ofs <<= 1) {
        int add = (t >= ofs) ? sm[t - ofs] : 0;
        __syncthreads();
        sm[t] += add;
        __syncthreads();
    }
    if (i < n) off[i] = sm[t] - v;
    if (t == 1023) partial[blockIdx.x] = sm[t];
}

__global__ void scan2_kernel(int* __restrict__ partial, int nb) {
    __shared__ int sm[256];
    int t = threadIdx.x;
    int v = (t < nb) ? partial[t] : 0;
    sm[t] = v;
    __syncthreads();
#pragma unroll
    for (int ofs = 1; ofs < 256; ofs <<= 1) {
        int add = (t >= ofs) ? sm[t - ofs] : 0;
        __syncthreads();
        sm[t] += add;
        __syncthreads();
    }
    if (t < nb) partial[t] = sm[t] - v;
}

// Finalize offsets + cursors + dinv in one pass.
__global__ void scan3_kernel(int* __restrict__ off, const int* __restrict__ partial,
                             int* __restrict__ cursor, const int* __restrict__ cnt,
                             float* __restrict__ dinv, int n) {
    int i = blockIdx.x * blockDim.x + threadIdx.x;
    if (i < n) {
        int o = off[i] + partial[i >> 10];
        off[i] = o;
        cursor[i] = o;
        dinv[i] = rsqrtf(1.0f + (float)cnt[i]);
    }
}

__global__ void fill_kernel(const int* __restrict__ ei, int E,
                            int* __restrict__ cursor, int* __restrict__ csr_src) {
    int e = blockIdx.x * blockDim.x + threadIdx.x;
    if (e < E) {
        int s = ei[e];
        int d = ei[E + e];
        int pos = atomicAdd(&cursor[d], 1);
        csr_src[pos] = s;
    }
}

__global__ void zero_cnt_kernel(int* __restrict__ cnt, int n) {
    int i = blockIdx.x * blockDim.x + threadIdx.x;
    if (i < n) cnt[i] = 0;
}

// ---------------------------------------------------------------------------
// Aggregation (GCN norm + self loop), thread per (node, 4 channels).
// agg[v,c] = dinv[v]^2*X[v,c] + sum_u dinv[u]*dinv[v]*X[u,c]
// 8-edge unroll: 24 independent loads in flight per iteration.
// ---------------------------------------------------------------------------
template <int C4>  // channels/4
__global__ void __launch_bounds__(256)
agg_kernel(const int* __restrict__ off, const int* __restrict__ cnt,
           const int* __restrict__ csr_src, const float* __restrict__ dinv,
           const float* __restrict__ X, float* __restrict__ out, int n) {
    int idx = blockIdx.x * blockDim.x + threadIdx.x;
    int node = idx / C4;
    int c4 = idx - node * C4;
    if (node >= n) return;

    const float4* X4 = reinterpret_cast<const float4*>(X);
    float dd = dinv[node];
    float4 x0 = __ldg(X4 + (size_t)node * C4 + c4);
    float s2 = dd * dd;
    float4 acc = make_float4(x0.x * s2, x0.y * s2, x0.z * s2, x0.w * s2);

    int start = off[node];
    int deg = cnt[node];
    const int* cp = csr_src + start;

    int j = 0;
    for (; j + 8 <= deg; j += 8) {
        int s[8];
#pragma unroll
        for (int k = 0; k < 8; k++) s[k] = __ldg(cp + j + k);
        float w[8];
#pragma unroll
        for (int k = 0; k < 8; k++) w[k] = __ldg(dinv + s[k]) * dd;
        float4 h[8];
#pragma unroll
        for (int k = 0; k < 8; k++) h[k] = __ldg(X4 + (size_t)s[k] * C4 + c4);
#pragma unroll
        for (int k = 0; k < 8; k++) {
            acc.x = fmaf(w[k], h[k].x, acc.x);
            acc.y = fmaf(w[k], h[k].y, acc.y);
            acc.z = fmaf(w[k], h[k].z, acc.z);
            acc.w = fmaf(w[k], h[k].w, acc.w);
        }
    }
    for (; j < deg; j++) {
        int s = __ldg(cp + j);
        float w = __ldg(dinv + s) * dd;
        float4 hv = __ldg(X4 + (size_t)s * C4 + c4);
        acc.x = fmaf(w, hv.x, acc.x);
        acc.y = fmaf(w, hv.y, acc.y);
        acc.z = fmaf(w, hv.z, acc.z);
        acc.w = fmaf(w, hv.w, acc.w);
    }
    reinterpret_cast<float4*>(out)[(size_t)node * C4 + c4] = acc;
}

// ---------------------------------------------------------------------------
// GEMM on k-pair-interleaved weights: C[n,K] = A[n,M] @ W[M,K].
// 4 nodes x 4 cols per thread, regs ~80, no spills (validated R14).
// A read as ulonglong2 (native f32 pairs — no packing movs); fma.rn.f32x2
// accumulates even-m lo / odd-m hi; halves summed in the epilogue.
// EPI: 1 bias+relu, 2 bias, 3 bias+BN+relu.
// ---------------------------------------------------------------------------
#define FMA2(acc, a, w) \
    asm("fma.rn.f32x2 %0, %1, %2, %0;" : "+l"(acc) : "l"(a), "l"(w))

template <int M, int K, int EPI>
__global__ void __launch_bounds__(128, 6)
gemm4p_kernel(const float* __restrict__ A, const unsigned long long* __restrict__ Wp,
              const float* __restrict__ bias, const float* __restrict__ gamma,
              const float* __restrict__ beta, float* __restrict__ C, int n) {
    constexpr int KC = K / 4;
    constexpr int MS = M / 4;  // ulonglong2 per A row
    int idx = blockIdx.x * blockDim.x + threadIdx.x;
    int ng = idx / KC;
    int c4 = idx - ng * KC;
    int n0 = ng * 4;
    if (n0 >= n) return;

    int ni[4];
#pragma unroll
    for (int i = 0; i < 4; i++) ni[i] = (n0 + i < n) ? (n0 + i) : n0;

    const ulonglong2* A2 = reinterpret_cast<const ulonglong2*>(A);
    unsigned long long acc[4][4] = {};

#pragma unroll 4
    for (int m4 = 0; m4 < MS; m4++) {
        ulonglong2 av[4];
#pragma unroll
        for (int i = 0; i < 4; i++)
            av[i] = __ldg(A2 + (size_t)ni[i] * MS + m4);
        const ulonglong2* w0p = reinterpret_cast<const ulonglong2*>(
            Wp + (size_t)(2 * m4) * K) + c4 * 2;
        const ulonglong2* w1p = reinterpret_cast<const ulonglong2*>(
            Wp + (size_t)(2 * m4 + 1) * K) + c4 * 2;
        ulonglong2 w0a = __ldg(w0p), w0b = __ldg(w0p + 1);
        ulonglong2 w1a = __ldg(w1p), w1b = __ldg(w1p + 1);
        unsigned long long w0[4] = {w0a.x, w0a.y, w0b.x, w0b.y};
        unsigned long long w1[4] = {w1a.x, w1a.y, w1b.x, w1b.y};
#pragma unroll
        for (int i = 0; i < 4; i++) {
#pragma unroll
            for (int c = 0; c < 4; c++) {
                FMA2(acc[i][c], av[i].x, w0[c]);
                FMA2(acc[i][c], av[i].y, w1[c]);
            }
        }
    }

    float4 bv = make_float4(0.f, 0.f, 0.f, 0.f);
    float4 gs = make_float4(0.f, 0.f, 0.f, 0.f);
    float4 bev = make_float4(0.f, 0.f, 0.f, 0.f);
    if (EPI >= 1) bv = reinterpret_cast<const float4*>(bias)[c4];
    if (EPI == 3) {
        const float INV = 0.99999500003749971f;  // 1/sqrt(1+1e-5)
        float4 gv = reinterpret_cast<const float4*>(gamma)[c4];
        gs = make_float4(gv.x * INV, gv.y * INV, gv.z * INV, gv.w * INV);
        bev = reinterpret_cast<const float4*>(beta)[c4];
    }

#pragma unroll
    for (int i = 0; i < 4; i++) {
        int node = n0 + i;
        if (node >= n) break;
        float o[4];
#pragma unroll
        for (int c = 0; c < 4; c++) {
            unsigned long long v = acc[i][c];
            o[c] = __uint_as_float((unsigned int)v) +
                   __uint_as_float((unsigned int)(v >> 32));
        }
        float4 r = make_float4(o[0], o[1], o[2], o[3]);
        if (EPI == 1 || EPI == 2) {
            r.x += bv.x; r.y += bv.y; r.z += bv.z; r.w += bv.w;
            if (EPI == 1) {
                r.x = fmaxf(r.x, 0.f); r.y = fmaxf(r.y, 0.f);
                r.z = fmaxf(r.z, 0.f); r.w = fmaxf(r.w, 0.f);
            }
        } else if (EPI == 3) {
            r.x = fmaxf(fmaf(r.x + bv.x, gs.x, bev.x), 0.f);
            r.y = fmaxf(fmaf(r.y + bv.y, gs.y, bev.y), 0.f);
            r.z = fmaxf(fmaf(r.z + bv.z, gs.z, bev.z), 0.f);
            r.w = fmaxf(fmaf(r.w + bv.w, gs.w, bev.w), 0.f);
        }
        reinterpret_cast<float4*>(C)[(size_t)node * KC + c4] = r;
    }
}

// ---------------------------------------------------------------------------
// Launch
// ---------------------------------------------------------------------------
static inline int grid_for(long long threads, int block) {
    return (int)((threads + block - 1) / block);
}

extern "C" void kernel_launch(void* const* d_in, const int* in_sizes, int n_in,
                              void* d_out, int out_size) {
    const float* x  = (const float*)d_in[0];
    const int*   ei = (const int*)d_in[1];
    const float* w1 = (const float*)d_in[2];
    const float* b1 = (const float*)d_in[3];
    const float* g1 = (const float*)d_in[4];
    const float* be1 = (const float*)d_in[5];
    const float* w2 = (const float*)d_in[6];
    const float* b2 = (const float*)d_in[7];
    const float* g2 = (const float*)d_in[8];
    const float* be2 = (const float*)d_in[9];
    const float* w3 = (const float*)d_in[10];
    const float* b3 = (const float*)d_in[11];
    const float* g3 = (const float*)d_in[12];
    const float* be3 = (const float*)d_in[13];
    const float* lw1 = (const float*)d_in[14];
    const float* lb1 = (const float*)d_in[15];
    const float* lw2 = (const float*)d_in[16];
    const float* lb2 = (const float*)d_in[17];
    const float* lw3 = (const float*)d_in[18];
    const float* lb3 = (const float*)d_in[19];
    const float* lw4 = (const float*)d_in[20];
    const float* lb4 = (const float*)d_in[21];
    float* out = (float*)d_out;

    const int N = in_sizes[0] / 64;
    const int E = in_sizes[1] / 2;

    int *cnt, *off, *cursor, *partial, *csr_src;
    float *dinv, *agg, *bufA, *bufB;
    unsigned long long* wp;
    cudaGetSymbolAddress((void**)&cnt,     g_cnt);
    cudaGetSymbolAddress((void**)&off,     g_off);
    cudaGetSymbolAddress((void**)&cursor,  g_cursor);
    cudaGetSymbolAddress((void**)&partial, g_partial);
    cudaGetSymbolAddress((void**)&csr_src, g_csr_src);
    cudaGetSymbolAddress((void**)&dinv,    g_dinv);
    cudaGetSymbolAddress((void**)&agg,     g_agg);
    cudaGetSymbolAddress((void**)&bufA,    g_bufA);
    cudaGetSymbolAddress((void**)&bufB,    g_bufB);
    cudaGetSymbolAddress((void**)&wp,      g_wp);

    const int BLK = 256;
    const int GB = 128;
    const int nb = (N + 1023) / 1024;
    const long long ngrp = (N + 3) / 4;

    // 0: interleave weights into k-pair layout.
    WSegs segs;
    segs.s[0] = {w1,  96,  OW1, 32 * 96};
    segs.s[1] = {w2,  96,  OW2, 48 * 96};
    segs.s[2] = {w3,  96,  OW3, 48 * 96};
    segs.s[3] = {lw1, 256, OL1, 48 * 256};
    segs.s[4] = {lw2, 128, OL2, 128 * 128};
    segs.s[5] = {lw3, 64,  OL3, 64 * 64};
    segs.s[6] = {lw4, 8,   OL4, 32 * 8};
    interleave_kernel<<<grid_for(WPTOT, BLK), BLK>>>(segs, wp);

    // CSR build.
    count_kernel<<<grid_for(E, BLK), BLK>>>(ei, E, cnt);
    scan1_kernel<<<nb, 1024>>>(cnt, N, off, partial);
    scan2_kernel<<<1, 256>>>(partial, nb);
    scan3_kernel<<<grid_for(N, BLK), BLK>>>(off, partial, cursor, cnt, dinv, N);
    fill_kernel<<<grid_for(E, BLK), BLK>>>(ei, E, cursor, csr_src);

    // GCN layer 1: aggregate x (64ch) first, then GEMM 64->96 + BN+ReLU.
    agg_kernel<16><<<grid_for((long long)N * 16, BLK), BLK>>>(off, cnt, csr_src, dinv, x, agg, N);
    gemm4p_kernel<64, 96, 3><<<grid_for(ngrp * 24, GB), GB>>>(agg, wp + OW1, b1, g1, be1, bufA, N);

    // GCN layer 2.
    agg_kernel<24><<<grid_for((long long)N * 24, BLK), BLK>>>(off, cnt, csr_src, dinv, bufA, agg, N);
    gemm4p_kernel<96, 96, 3><<<grid_for(ngrp * 24, GB), GB>>>(agg, wp + OW2, b2, g2, be2, bufB, N);

    // GCN layer 3.
    agg_kernel<24><<<grid_for((long long)N * 24, BLK), BLK>>>(off, cnt, csr_src, dinv, bufB, agg, N);
    gemm4p_kernel<96, 96, 3><<<grid_for(ngrp * 24, GB), GB>>>(agg, wp + OW3, b3, g3, be3, bufA, N);

    // MLP head.
    gemm4p_kernel<96, 256, 1><<<grid_for(ngrp * 64, GB), GB>>>(bufA, wp + OL1, lb1, nullptr, nullptr, bufB, N);
    gemm4p_kernel<256, 128, 1><<<grid_for(ngrp * 32, GB), GB>>>(bufB, wp + OL2, lb2, nullptr, nullptr, bufA, N);
    gemm4p_kernel<128, 64, 1><<<grid_for(ngrp * 16, GB), GB>>>(bufA, wp + OL3, lb3, nullptr, nullptr, bufB, N);
    gemm4p_kernel<64, 8, 2><<<grid_for(ngrp * 2, GB), GB>>>(bufB, wp + OL4, lb4, nullptr, nullptr, out, N);

    // Reset cnt for next replay.
    zero_cnt_kernel<<<grid_for(N, BLK), BLK>>>(cnt, N);
}